// round 9
// baseline (speedup 1.0000x reference)
#include <cuda_runtime.h>
#include <cuda_fp16.h>
#include <cstdint>

#define MBLK 64
#define PDIM 256
#define BATCH 4096
#define ROWSTRIDE 16384            // halves/floats per batch row

#define TILE_M 128
#define TILE_N 256
#define BK 128                     // halves per chunk (256B data rows)
#define NCHUNK 6                   // 3 segments * 256/128
#define NSTAGE 2

#define HROW 272                   // padded row stride bytes (256 data + 16 pad)
#define SA_BYTES (TILE_M * HROW)   // 34816
#define SB_BYTES (TILE_N * HROW)   // 69632
#define STAGE_BYTES (SA_BYTES + SB_BYTES)   // 104448
#define SMEM_BYTES (STAGE_BYTES * NSTAGE)   // 208896

__device__ __half g_xh[(size_t)BATCH * ROWSTRIDE];        // 134 MB
__device__ __half g_wh[(size_t)192 * PDIM * PDIM];        // 25 MB

__device__ __forceinline__ uint32_t smem_u32(const void* p) {
    uint32_t a;
    asm("{ .reg .u64 t; cvta.to.shared.u64 t, %1; cvt.u32.u64 %0, t; }" : "=r"(a) : "l"(p));
    return a;
}
__device__ __forceinline__ void cp16(uint32_t dst, const void* src) {
    asm volatile("cp.async.cg.shared.global [%0], [%1], 16;\n" :: "r"(dst), "l"(src));
}
__device__ __forceinline__ void cp_commit() {
    asm volatile("cp.async.commit_group;\n" ::: "memory");
}
template <int N>
__device__ __forceinline__ void cp_wait() {
    asm volatile("cp.async.wait_group %0;\n" :: "n"(N) : "memory");
}
__device__ __forceinline__ void ldsm4(uint32_t* r, uint32_t addr) {
    asm volatile("ldmatrix.sync.aligned.m8n8.x4.shared.b16 {%0,%1,%2,%3}, [%4];\n"
                 : "=r"(r[0]), "=r"(r[1]), "=r"(r[2]), "=r"(r[3]) : "r"(addr));
}
__device__ __forceinline__ void mma16(float* c,
                                      uint32_t a0, uint32_t a1, uint32_t a2, uint32_t a3,
                                      uint32_t b0, uint32_t b1) {
    asm volatile(
        "mma.sync.aligned.m16n8k16.row.col.f32.f16.f16.f32 "
        "{%0,%1,%2,%3}, {%4,%5,%6,%7}, {%8,%9}, {%0,%1,%2,%3};\n"
        : "+f"(c[0]), "+f"(c[1]), "+f"(c[2]), "+f"(c[3])
        : "r"(a0), "r"(a1), "r"(a2), "r"(a3), "r"(b0), "r"(b1));
}

// ---------------- prologue converters (16 elems/thread) ----------------
__global__ void __launch_bounds__(256) cvt_x_kernel(const float* __restrict__ src) {
    size_t i = ((size_t)blockIdx.x * 256 + threadIdx.x) * 16;
    #pragma unroll
    for (int p = 0; p < 2; ++p) {
        float4 v0 = *reinterpret_cast<const float4*>(src + i + p * 8);
        float4 v1 = *reinterpret_cast<const float4*>(src + i + p * 8 + 4);
        __half2 h[4] = { __floats2half2_rn(v0.x, v0.y), __floats2half2_rn(v0.z, v0.w),
                         __floats2half2_rn(v1.x, v1.y), __floats2half2_rn(v1.z, v1.w) };
        *reinterpret_cast<uint4*>(g_xh + i + p * 8) = *reinterpret_cast<uint4*>(h);
    }
}
__global__ void __launch_bounds__(256) cvt_w_kernel(const float* __restrict__ src, size_t dstoff) {
    size_t i = ((size_t)blockIdx.x * 256 + threadIdx.x) * 16;
    #pragma unroll
    for (int p = 0; p < 2; ++p) {
        float4 v0 = *reinterpret_cast<const float4*>(src + i + p * 8);
        float4 v1 = *reinterpret_cast<const float4*>(src + i + p * 8 + 4);
        __half2 h[4] = { __floats2half2_rn(v0.x, v0.y), __floats2half2_rn(v0.z, v0.w),
                         __floats2half2_rn(v1.x, v1.y), __floats2half2_rn(v1.z, v1.w) };
        *reinterpret_cast<uint4*>(g_wh + dstoff + i + p * 8) = *reinterpret_cast<uint4*>(h);
    }
}

__device__ __forceinline__ int seg_wblk(int s, int i, int& j) {
    if (s == 0) { j = i;            return i; }
    if (s == 1) { j = (i + 1) & 63; return (i < 63) ? 64 + i : 191; }
    j = (i + 63) & 63;              return (i > 0) ? 127 + (i - 1) : 190;
}

// ---------------- main GEMM: 512 threads, BK=128, 2 stages ----------------
__global__ void __launch_bounds__(512, 1)
bxdiag_h16_kernel(float* __restrict__ out)
{
    extern __shared__ __align__(128) char smem[];
    const uint32_t sbase = smem_u32(smem);

    const int tid = threadIdx.x;
    const int wid = tid >> 5;
    const int lid = tid & 31;
    const int wm  = wid & 3;       // 0..3 : 32-row quarter
    const int wn  = wid >> 2;      // 0..3 : 64-col quarter
    const int bt  = blockIdx.x;
    const int i   = blockIdx.y;
    const int row0 = bt * TILE_M;

    auto issue_stage = [&](int c) {
        const int s  = c >> 1;                 // 0..2
        const int k0 = (c & 1) * BK;
        int j;
        const int wblk = seg_wblk(s, i, j);
        const __half* xsrc = g_xh + (size_t)row0 * ROWSTRIDE + j * PDIM + k0;
        const __half* wsrc = g_wh + (size_t)wblk * (PDIM * PDIM) + k0;
        const uint32_t ab = sbase + (uint32_t)((c & 1 ^ (c >> 1 & 1) ^ c) , 0);
        (void)ab;
        const uint32_t a0 = sbase + (uint32_t)((c % NSTAGE) * STAGE_BYTES);
        const uint32_t b0 = a0 + SA_BYTES;
        #pragma unroll
        for (int it = 0; it < 4; ++it) {       // A: 128 rows x 16 x 16B = 2048
            const int ch = tid + it * 512;
            const int r = ch >> 4, cc = ch & 15;
            cp16(a0 + (uint32_t)(r * HROW + cc * 16),
                 xsrc + (size_t)r * ROWSTRIDE + cc * 8);
        }
        #pragma unroll
        for (int it = 0; it < 8; ++it) {       // B: 256 rows x 16 x 16B = 4096
            const int ch = tid + it * 512;
            const int r = ch >> 4, cc = ch & 15;
            cp16(b0 + (uint32_t)(r * HROW + cc * 16),
                 wsrc + r * PDIM + cc * 8);
        }
    };

    float acc[2][8][4];
    #pragma unroll
    for (int mt = 0; mt < 2; ++mt)
        #pragma unroll
        for (int nt = 0; nt < 8; ++nt)
            #pragma unroll
            for (int q = 0; q < 4; ++q)
                acc[mt][nt][q] = 0.0f;

    issue_stage(0); cp_commit();
    issue_stage(1); cp_commit();

    const int sub    = lid >> 3;
    const int rowoff = ((sub & 1) << 3) + (lid & 7);
    const int koff   = (sub >> 1) << 3;        // 0 or 8 halves

    #pragma unroll 1
    for (int c = 0; c < NCHUNK; ++c) {
        cp_wait<1>();
        __syncthreads();                       // stage c resident

        const uint32_t fa = sbase + (uint32_t)((c % NSTAGE) * STAGE_BYTES);
        const uint32_t fb = fa + SA_BYTES;

        #pragma unroll
        for (int k16 = 0; k16 < BK / 16; ++k16) {
            const int kc = k16 * 16 + koff;
            uint32_t af[2][4], bf[4][4];
            #pragma unroll
            for (int mt = 0; mt < 2; ++mt)
                ldsm4(af[mt], fa + (uint32_t)((wm * 32 + mt * 16 + rowoff) * HROW + kc * 2));
            #pragma unroll
            for (int nt = 0; nt < 4; ++nt)
                ldsm4(bf[nt], fb + (uint32_t)((wn * 64 + nt * 16 + rowoff) * HROW + kc * 2));
            #pragma unroll
            for (int mt = 0; mt < 2; ++mt)
                #pragma unroll
                for (int nt = 0; nt < 4; ++nt) {
                    mma16(acc[mt][nt * 2 + 0], af[mt][0], af[mt][1], af[mt][2], af[mt][3],
                          bf[nt][0], bf[nt][2]);
                    mma16(acc[mt][nt * 2 + 1], af[mt][0], af[mt][1], af[mt][2], af[mt][3],
                          bf[nt][1], bf[nt][3]);
                }
        }

        __syncthreads();                       // stage buffer free
        if (c + 2 < NCHUNK) issue_stage(c + 2);
        cp_commit();
    }

    const int g  = lid >> 2;
    const int tg = lid & 3;
    float* ob = out + (size_t)row0 * ROWSTRIDE + i * PDIM;
    #pragma unroll
    for (int mt = 0; mt < 2; ++mt) {
        #pragma unroll
        for (int nt = 0; nt < 8; ++nt) {
            const int r0 = wm * 32 + mt * 16 + g;
            const int cc = wn * 64 + nt * 8 + tg * 2;
            float2 v0 = make_float2(acc[mt][nt][0], acc[mt][nt][1]);
            float2 v1 = make_float2(acc[mt][nt][2], acc[mt][nt][3]);
            *reinterpret_cast<float2*>(ob + (size_t)r0 * ROWSTRIDE + cc) = v0;
            *reinterpret_cast<float2*>(ob + (size_t)(r0 + 8) * ROWSTRIDE + cc) = v1;
        }
    }
}

extern "C" void kernel_launch(void* const* d_in, const int* in_sizes, int n_in,
                              void* d_out, int out_size)
{
    const float* x   = (const float*)d_in[0];
    const float* Wd  = (const float*)d_in[1];
    const float* Wu  = (const float*)d_in[2];
    const float* Wl  = (const float*)d_in[3];
    const float* Wtr = (const float*)d_in[4];
    const float* Wbl = (const float*)d_in[5];
    float* out = (float*)d_out;

    const size_t PB = (size_t)PDIM * PDIM;
    cvt_x_kernel<<<(unsigned)((size_t)BATCH * ROWSTRIDE / 4096), 256>>>(x);
    cvt_w_kernel<<<(unsigned)(64 * PB / 4096), 256>>>(Wd, 0);
    cvt_w_kernel<<<(unsigned)(63 * PB / 4096), 256>>>(Wu, 64 * PB);
    cvt_w_kernel<<<(unsigned)(63 * PB / 4096), 256>>>(Wl, 127 * PB);
    cvt_w_kernel<<<(unsigned)(PB / 4096), 256>>>(Wtr, 190 * PB);
    cvt_w_kernel<<<(unsigned)(PB / 4096), 256>>>(Wbl, 191 * PB);

    cudaFuncSetAttribute(bxdiag_h16_kernel,
                         cudaFuncAttributeMaxDynamicSharedMemorySize, SMEM_BYTES);
    dim3 grid(BATCH / TILE_M, MBLK);           // 32 x 64 = 2048 CTAs
    bxdiag_h16_kernel<<<grid, 512, SMEM_BYTES>>>(out);
}